// round 16
// baseline (speedup 1.0000x reference)
#include <cuda_runtime.h>
#include <cuda_bf16.h>
#include <cstdint>
#include <cstddef>

#define DIMM    768
#define MTOK    4096
#define NSEQ    1024
#define NHEADS  12
#define DHEAD   64
#define FFI     2048
#define BHTOT   48

// ---------------- scratch (static device globals; no allocation) -------------
__device__ float g_q [MTOK * DIMM];
__device__ float g_kv[MTOK * 2 * DIMM];
__device__ __align__(16) float g_u [MTOK * 2 * FFI];   // reused as bf16 gh/gl
__device__ __align__(16) __nv_bfloat16 g_ah [MTOK * FFI];
__device__ __align__(16) __nv_bfloat16 g_al [MTOK * FFI];
__device__ __align__(16) __nv_bfloat16 g_xh [MTOK * DIMM];
__device__ __align__(16) __nv_bfloat16 g_xl [MTOK * DIMM];
__device__ __align__(16) __nv_bfloat16 g_wth [4096 * 768];  // ff1
__device__ __align__(16) __nv_bfloat16 g_wtl [4096 * 768];
__device__ __align__(16) __nv_bfloat16 g_wth2[2048 * 768];  // ff2
__device__ __align__(16) __nv_bfloat16 g_wtl2[2048 * 768];
__device__ __align__(16) __nv_bfloat16 g_wtqh[768 * 768];   // wq
__device__ __align__(16) __nv_bfloat16 g_wtql[768 * 768];
__device__ __align__(16) __nv_bfloat16 g_wtoh[768 * 768];   // wo
__device__ __align__(16) __nv_bfloat16 g_wtol[768 * 768];
__device__ __align__(16) __nv_bfloat16 g_wtkh[1536 * 768];  // wkv
__device__ __align__(16) __nv_bfloat16 g_wtkl[1536 * 768];
__device__ __align__(16) __nv_bfloat16 g_qh [BHTOT * NSEQ * DHEAD];
__device__ __align__(16) __nv_bfloat16 g_ql [BHTOT * NSEQ * DHEAD];
__device__ __align__(16) __nv_bfloat16 g_kh [BHTOT * NSEQ * DHEAD];
__device__ __align__(16) __nv_bfloat16 g_kl [BHTOT * NSEQ * DHEAD];
__device__ __align__(16) __nv_bfloat16 g_vh [BHTOT * NSEQ * DHEAD]; // [bh][d][n]
__device__ __align__(16) __nv_bfloat16 g_vl [BHTOT * NSEQ * DHEAD];

// =========================== PTX helpers (sm_80-safe) =========================
__device__ __forceinline__ uint32_t smem_to_u32(const void* p) {
    uint32_t a;
    asm("{ .reg .u64 t; cvta.to.shared.u64 t, %1; cvt.u32.u64 %0, t; }"
        : "=r"(a) : "l"(p));
    return a;
}
#define CPASYNC(d, s) \
    asm volatile("cp.async.cg.shared.global [%0], [%1], 16;" :: "r"(d), "l"(s))
#define CPCOMMIT() asm volatile("cp.async.commit_group;" ::: "memory")
#define CPWAIT2()  asm volatile("cp.async.wait_group 2;" ::: "memory")
#define CPWAIT1()  asm volatile("cp.async.wait_group 1;" ::: "memory")
#define CPWAIT0()  asm volatile("cp.async.wait_group 0;" ::: "memory")
#define LDSM4(r, addr) \
    asm volatile("ldmatrix.sync.aligned.m8n8.x4.shared.b16 {%0,%1,%2,%3}, [%4];" \
        : "=r"((r)[0]), "=r"((r)[1]), "=r"((r)[2]), "=r"((r)[3]) : "r"(addr))
#define MMA_BF16(d, a, b0, b1) \
    asm volatile("mma.sync.aligned.m16n8k16.row.col.f32.bf16.bf16.f32 " \
        "{%0,%1,%2,%3}, {%4,%5,%6,%7}, {%8,%9}, {%0,%1,%2,%3};" \
        : "+f"((d)[0]), "+f"((d)[1]), "+f"((d)[2]), "+f"((d)[3]) \
        : "r"((a)[0]), "r"((a)[1]), "r"((a)[2]), "r"((a)[3]), "r"(b0), "r"(b1))

__device__ __forceinline__ void bsplit(float v, __nv_bfloat16& h, __nv_bfloat16& l) {
    h = __float2bfloat16(v);
    l = __float2bfloat16(v - __bfloat162float(h));
}
__device__ __forceinline__ uint32_t pack2(__nv_bfloat16 a, __nv_bfloat16 b) {
    return (uint32_t)__bfloat16_as_ushort(a) |
           ((uint32_t)__bfloat16_as_ushort(b) << 16);
}
// fast exp for y <= 0 (poly 2^f, magic-number split); rel err ~3e-6
__device__ __forceinline__ float fexp(float y) {
    float t = fmaxf(y * 1.4426950408889634f, -60.0f);
    float z = t + 12582912.0f;
    int   i = __float_as_int(z) - 0x4B400000;
    float f = t - (z - 12582912.0f);
    float p = 1.3333558146e-3f;
    p = fmaf(p, f, 9.6181291076e-3f);
    p = fmaf(p, f, 5.5504108664e-2f);
    p = fmaf(p, f, 2.4022650696e-1f);
    p = fmaf(p, f, 6.9314718056e-1f);
    p = fmaf(p, f, 1.0f);
    return __int_as_float(__float_as_int(p) + (i << 23));
}

// ------------------------- LayerNorm -> split bf16 ---------------------------
__global__ void __launch_bounds__(256) ln_kernel(
    const float* __restrict__ x, const float* __restrict__ gamma,
    const float* __restrict__ beta,
    __nv_bfloat16* __restrict__ oh, __nv_bfloat16* __restrict__ ol)
{
    int row = blockIdx.x, tid = threadIdx.x;
    const float* xr = x + (size_t)row * DIMM;
    float v0 = xr[tid], v1 = xr[tid + 256], v2 = xr[tid + 512];
    float s = v0 + v1 + v2, sq = v0 * v0 + v1 * v1 + v2 * v2;
#pragma unroll
    for (int o = 16; o > 0; o >>= 1) {
        s  += __shfl_xor_sync(0xffffffffu, s, o);
        sq += __shfl_xor_sync(0xffffffffu, sq, o);
    }
    __shared__ float red[16];
    if ((tid & 31) == 0) { red[tid >> 5] = s; red[(tid >> 5) + 8] = sq; }
    __syncthreads();
    float ts = 0.f, tq = 0.f;
#pragma unroll
    for (int i = 0; i < 8; i++) { ts += red[i]; tq += red[i + 8]; }
    float mu  = ts * (1.0f / 768.0f);
    float var = tq * (1.0f / 768.0f) - mu * mu;
    float inv = rsqrtf(var + 1e-5f);
    size_t base = (size_t)row * DIMM;
#pragma unroll
    for (int i = 0; i < 3; i++) {
        int c = tid + i * 256;
        float vv = (i == 0 ? v0 : (i == 1 ? v1 : v2));
        float b = beta ? beta[c] : 0.f;
        float y = (vv - mu) * inv * gamma[c] + b;
        __nv_bfloat16 h, l; bsplit(y, h, l);
        oh[base + c] = h; ol[base + c] = l;
    }
}

// ---------------- weight transpose + split: W[K,N] -> Wt[N,K] hi/lo ----------
__global__ void __launch_bounds__(256) wtrans_kernel(
    const float* __restrict__ W, __nv_bfloat16* __restrict__ th,
    __nv_bfloat16* __restrict__ tl, int Kd, int Nd, int ilv)
{
    __shared__ float t[32][33];
    int tx = threadIdx.x & 31, ty = threadIdx.x >> 5;
    int n0 = blockIdx.x * 32, k0 = blockIdx.y * 32;
#pragma unroll
    for (int i = 0; i < 4; i++)
        t[ty + i * 8][tx] = W[(size_t)(k0 + ty + i * 8) * Nd + n0 + tx];
    __syncthreads();
#pragma unroll
    for (int i = 0; i < 4; i++) {
        int n = n0 + ty + i * 8;
        int np = ilv ? ((n < (Nd >> 1)) ? (2 * n) : (2 * (n - (Nd >> 1)) + 1)) : n;
        float v = t[tx][ty + i * 8];
        __nv_bfloat16 h, l; bsplit(v, h, l);
        th[(size_t)np * Kd + k0 + tx] = h;
        tl[(size_t)np * Kd + k0 + tx] = l;
    }
}

// --------------------------- fp32 -> split bf16 ------------------------------
__global__ void __launch_bounds__(256) split_kernel(
    const float* __restrict__ x, __nv_bfloat16* __restrict__ oh,
    __nv_bfloat16* __restrict__ ol)
{
    int i = blockIdx.x * 256 + threadIdx.x;
    __nv_bfloat16 h, l; bsplit(x[i], h, l);
    oh[i] = h; ol[i] = l;
}

// ------------- RoPE + l2norm + scale (+8x for Q) -> split bf16 ---------------
__global__ void __launch_bounds__(256) rope_split_kernel(
    const float* __restrict__ src, int srcStride,
    const float* __restrict__ scale, float mult,
    __nv_bfloat16* __restrict__ dh, __nv_bfloat16* __restrict__ dl)
{
    int row = blockIdx.x, tid = threadIdx.x;
    int hh = tid >> 6, head = blockIdx.y * 4 + hh, d = tid & 63;
    int n = row & 1023, b = row >> 10;
    float v = src[(size_t)row * srcStride + head * DHEAD + d];
    int j = d >> 1, t = j >> 1;
    float p = (j & 1) ? (float)(n >> 5) : (float)(n & 31);
    float ang = p * exp2f(-0.830482024f * (float)t);
    float c = cosf(ang), s = sinf(ang);
    float other = __shfl_xor_sync(0xffffffffu, v, 1);
    float out = (d & 1) ? (other * s + v * c) : (v * c - other * s);
    float ss = out * out;
#pragma unroll
    for (int o = 16; o > 0; o >>= 1) ss += __shfl_xor_sync(0xffffffffu, ss, o);
    __shared__ float s8[8];
    if ((tid & 31) == 0) s8[tid >> 5] = ss;
    __syncthreads();
    float inv = 1.0f / fmaxf(sqrtf(s8[hh * 2] + s8[hh * 2 + 1]), 1e-12f);
    out = out * inv * scale[d] * mult;
    __nv_bfloat16 h, l; bsplit(out, h, l);
    size_t idx = (((size_t)(b * NHEADS + head)) * NSEQ + n) * DHEAD + d;
    dh[idx] = h; dl[idx] = l;
}

// --------- V transpose + split: kv[.,768+c] -> Vt[bh][d][n] hi/lo -------------
__global__ void __launch_bounds__(256) vtrans_split_kernel(
    const float* __restrict__ kv, __nv_bfloat16* __restrict__ vh,
    __nv_bfloat16* __restrict__ vl)
{
    __shared__ float t[32][65];
    int tid = threadIdx.x, bh = blockIdx.y, n0 = blockIdx.x * 32;
    int b = bh / NHEADS, h = bh % NHEADS;
#pragma unroll
    for (int i = 0; i < 8; i++) {
        int nl = (tid >> 6) + i * 4, d = tid & 63;
        t[nl][d] = kv[(size_t)(b * NSEQ + n0 + nl) * (2 * DIMM) + DIMM + h * DHEAD + d];
    }
    __syncthreads();
#pragma unroll
    for (int i = 0; i < 8; i++) {
        int dd = (tid >> 5) + i * 8, nl = tid & 31;
        float v = t[nl][dd];
        __nv_bfloat16 hi, lo; bsplit(v, hi, lo);
        size_t idx = ((size_t)bh * DHEAD + dd) * NSEQ + n0 + nl;
        vh[idx] = hi; vl[idx] = lo;
    }
}

// ================= tensor-core flash attention (split-3 bf16) =================
#define AROW 72
__global__ void __launch_bounds__(128) attn_tc_kernel(
    const __nv_bfloat16* __restrict__ Qh, const __nv_bfloat16* __restrict__ Ql,
    const __nv_bfloat16* __restrict__ Kh, const __nv_bfloat16* __restrict__ Kl,
    const __nv_bfloat16* __restrict__ Vh, const __nv_bfloat16* __restrict__ Vl,
    __nv_bfloat16* __restrict__ Oh, __nv_bfloat16* __restrict__ Ol)
{
    __shared__ __align__(16) __nv_bfloat16 sKh[64 * AROW], sKl[64 * AROW];
    __shared__ __align__(16) __nv_bfloat16 sVh[64 * AROW], sVl[64 * AROW];
    __shared__ __align__(16) __nv_bfloat16 sPh[64 * AROW], sPl[64 * AROW];

    int tid = threadIdx.x, lane = tid & 31, w = tid >> 5;
    int bh = blockIdx.y, q0 = blockIdx.x * 64;
    const __nv_bfloat16* qh = Qh + ((size_t)bh * NSEQ + q0) * DHEAD;
    const __nv_bfloat16* ql = Ql + ((size_t)bh * NSEQ + q0) * DHEAD;
    const __nv_bfloat16* kh = Kh + (size_t)bh * NSEQ * DHEAD;
    const __nv_bfloat16* kl = Kl + (size_t)bh * NSEQ * DHEAD;
    const __nv_bfloat16* vh = Vh + (size_t)bh * DHEAD * NSEQ;
    const __nv_bfloat16* vl = Vl + (size_t)bh * DHEAD * NSEQ;
    uint32_t aKh = smem_to_u32(sKh), aKl = smem_to_u32(sKl);
    uint32_t aVh = smem_to_u32(sVh), aVl = smem_to_u32(sVl);
    uint32_t aPh = smem_to_u32(sPh), aPl = smem_to_u32(sPl);

#pragma unroll
    for (int i = 0; i < 4; i++) {
        int id = tid + i * 128, r = id >> 3, c8 = (id & 7) * 8;
        *reinterpret_cast<uint4*>(&sPh[r * AROW + c8]) =
            *reinterpret_cast<const uint4*>(qh + r * 64 + c8);
        *reinterpret_cast<uint4*>(&sPl[r * AROW + c8]) =
            *reinterpret_cast<const uint4*>(ql + r * 64 + c8);
    }
    __syncthreads();
    const int lj = lane >> 3, lr = lane & 7, m0 = w * 16;
    uint32_t qhf[4][4], qlf[4][4];
#pragma unroll
    for (int ks = 0; ks < 4; ks++) {
        uint32_t off = (uint32_t)((m0 + (lj & 1) * 8 + lr) * AROW +
                                  ks * 16 + (lj >> 1) * 8) * 2;
        LDSM4(qhf[ks], aPh + off);
        LDSM4(qlf[ks], aPl + off);
    }

    float m1 = -1e30f, m2 = -1e30f, l1 = 0.f, l2 = 0.f;
    float of[8][4];
#pragma unroll
    for (int nt = 0; nt < 8; nt++)
#pragma unroll
        for (int j = 0; j < 4; j++) of[nt][j] = 0.f;

    for (int kt = 0; kt < 16; kt++) {
        __syncthreads();
#pragma unroll
        for (int i = 0; i < 4; i++) {
            int c = tid + i * 128, r = c >> 3, u8 = (c & 7) * 8;
            uint32_t d = (uint32_t)(r * AROW + u8) * 2;
            CPASYNC(aKh + d, kh + (size_t)(kt * 64 + r) * 64 + u8);
            CPASYNC(aKl + d, kl + (size_t)(kt * 64 + r) * 64 + u8);
        }
        CPCOMMIT();
#pragma unroll
        for (int i = 0; i < 4; i++) {
            int c = tid + i * 128, r = c >> 3, u8 = (c & 7) * 8;
            uint32_t d = (uint32_t)(r * AROW + u8) * 2;
            CPASYNC(aVh + d, vh + (size_t)r * NSEQ + kt * 64 + u8);
            CPASYNC(aVl + d, vl + (size_t)r * NSEQ + kt * 64 + u8);
        }
        CPCOMMIT();
        CPWAIT1();
        __syncthreads();

        float sf[8][4];
#pragma unroll
        for (int nt = 0; nt < 8; nt++)
#pragma unroll
            for (int j = 0; j < 4; j++) sf[nt][j] = 0.f;
#pragma unroll
        for (int ks = 0; ks < 4; ks++) {
            uint32_t khf[4][4], klf[4][4];
#pragma unroll
            for (int bt = 0; bt < 4; bt++) {
                uint32_t off = (uint32_t)((bt * 16 + (lj >> 1) * 8 + lr) * AROW +
                                          ks * 16 + (lj & 1) * 8) * 2;
                LDSM4(khf[bt], aKh + off);
                LDSM4(klf[bt], aKl + off);
            }
#pragma unroll
            for (int bt = 0; bt < 4; bt++)
#pragma unroll
                for (int hf = 0; hf < 2; hf++)
                    MMA_BF16(sf[bt * 2 + hf], qhf[ks], khf[bt][hf * 2], khf[bt][hf * 2 + 1]);
#pragma unroll
            for (int bt = 0; bt < 4; bt++)
#pragma unroll
                for (int hf = 0; hf < 2; hf++)
                    MMA_BF16(sf[bt * 2 + hf], qhf[ks], klf[bt][hf * 2], klf[bt][hf * 2 + 1]);
#pragma unroll
            for (int bt = 0; bt < 4; bt++)
#pragma unroll
                for (int hf = 0; hf < 2; hf++)
                    MMA_BF16(sf[bt * 2 + hf], qlf[ks], khf[bt][hf * 2], khf[bt][hf * 2 + 1]);
        }

        float mx1 = -1e30f, mx2 = -1e30f;
#pragma unroll
        for (int nt = 0; nt < 8; nt++) {
            mx1 = fmaxf(mx1, fmaxf(sf[nt][0], sf[nt][1]));
            mx2 = fmaxf(mx2, fmaxf(sf[nt][2], sf[nt][3]));
        }
        mx1 = fmaxf(mx1, __shfl_xor_sync(0xffffffffu, mx1, 1));
        mx1 = fmaxf(mx1, __shfl_xor_sync(0xffffffffu, mx1, 2));
        mx2 = fmaxf(mx2, __shfl_xor_sync(0xffffffffu, mx2, 1));
        mx2 = fmaxf(mx2, __shfl_xor_sync(0xffffffffu, mx2, 2));
        float mn1 = fmaxf(m1, mx1), mn2 = fmaxf(m2, mx2);
        float c1 = fexp(m1 - mn1), c2 = fexp(m2 - mn2);
        float rs1 = 0.f, rs2 = 0.f;
#pragma unroll
        for (int nt = 0; nt < 8; nt++) {
            sf[nt][0] = fexp(sf[nt][0] - mn1);
            sf[nt][1] = fexp(sf[nt][1] - mn1);
            sf[nt][2] = fexp(sf[nt][2] - mn2);
            sf[nt][3] = fexp(sf[nt][3] - mn2);
            rs1 += sf[nt][0] + sf[nt][1];
            rs2 += sf[nt][2] + sf[nt][3];
        }
        rs1 += __shfl_xor_sync(0xffffffffu, rs1, 1);
        rs1 += __shfl_xor_sync(0xffffffffu, rs1, 2);
        rs2 += __shfl_xor_sync(0xffffffffu, rs2, 1);
        rs2 += __shfl_xor_sync(0xffffffffu, rs2, 2);
        l1 = l1 * c1 + rs1; l2 = l2 * c2 + rs2;
        m1 = mn1; m2 = mn2;
#pragma unroll
        for (int nt = 0; nt < 8; nt++) {
            of[nt][0] *= c1; of[nt][1] *= c1;
            of[nt][2] *= c2; of[nt][3] *= c2;
        }

        int r1 = m0 + (lane >> 2), r2 = r1 + 8, cc = (lane & 3) * 2;
#pragma unroll
        for (int nt = 0; nt < 8; nt++) {
            int col = nt * 8 + cc;
            __nv_bfloat16 h0, l0, h1, lo1;
            bsplit(sf[nt][0], h0, l0); bsplit(sf[nt][1], h1, lo1);
            *reinterpret_cast<uint32_t*>(&sPh[r1 * AROW + col]) = pack2(h0, h1);
            *reinterpret_cast<uint32_t*>(&sPl[r1 * AROW + col]) = pack2(l0, lo1);
            bsplit(sf[nt][2], h0, l0); bsplit(sf[nt][3], h1, lo1);
            *reinterpret_cast<uint32_t*>(&sPh[r2 * AROW + col]) = pack2(h0, h1);
            *reinterpret_cast<uint32_t*>(&sPl[r2 * AROW + col]) = pack2(l0, lo1);
        }
        __syncwarp();
        CPWAIT0();
        __syncthreads();

#pragma unroll
        for (int ks = 0; ks < 4; ks++) {
            uint32_t phf[4], plf[4], vhf[4][4], vlf[4][4];
            uint32_t offp = (uint32_t)((m0 + (lj & 1) * 8 + lr) * AROW +
                                       ks * 16 + (lj >> 1) * 8) * 2;
            LDSM4(phf, aPh + offp);
            LDSM4(plf, aPl + offp);
#pragma unroll
            for (int bt = 0; bt < 4; bt++) {
                uint32_t offv = (uint32_t)((bt * 16 + (lj >> 1) * 8 + lr) * AROW +
                                           ks * 16 + (lj & 1) * 8) * 2;
                LDSM4(vhf[bt], aVh + offv);
                LDSM4(vlf[bt], aVl + offv);
            }
#pragma unroll
            for (int bt = 0; bt < 4; bt++)
#pragma unroll
                for (int hf = 0; hf < 2; hf++)
                    MMA_BF16(of[bt * 2 + hf], phf, vhf[bt][hf * 2], vhf[bt][hf * 2 + 1]);
#pragma unroll
            for (int bt = 0; bt < 4; bt++)
#pragma unroll
                for (int hf = 0; hf < 2; hf++)
                    MMA_BF16(of[bt * 2 + hf], phf, vlf[bt][hf * 2], vlf[bt][hf * 2 + 1]);
#pragma unroll
            for (int bt = 0; bt < 4; bt++)
#pragma unroll
                for (int hf = 0; hf < 2; hf++)
                    MMA_BF16(of[bt * 2 + hf], plf, vhf[bt][hf * 2], vhf[bt][hf * 2 + 1]);
        }
    }

    int b = bh / NHEADS, hh = bh % NHEADS;
    float inv1 = 1.0f / l1, inv2 = 1.0f / l2;
    int r1 = q0 + m0 + (lane >> 2), cc = (lane & 3) * 2;
    size_t row1 = (size_t)(b * NSEQ + r1) * DIMM + hh * DHEAD;
    size_t row2 = (size_t)(b * NSEQ + r1 + 8) * DIMM + hh * DHEAD;
#pragma unroll
    for (int nt = 0; nt < 8; nt++) {
        int col = nt * 8 + cc;
        __nv_bfloat16 h0, l0, h1, lo1;
        bsplit(of[nt][0] * inv1, h0, l0); bsplit(of[nt][1] * inv1, h1, lo1);
        *reinterpret_cast<uint32_t*>(Oh + row1 + col) = pack2(h0, h1);
        *reinterpret_cast<uint32_t*>(Ol + row1 + col) = pack2(l0, lo1);
        bsplit(of[nt][2] * inv2, h0, l0); bsplit(of[nt][3] * inv2, h1, lo1);
        *reinterpret_cast<uint32_t*>(Oh + row2 + col) = pack2(h0, h1);
        *reinterpret_cast<uint32_t*>(Ol + row2 + col) = pack2(l0, lo1);
    }
}

// ====== HMMA GEMM: C = A@B^T (+res / split out / fused GELU-gate out) ========
#define SWZ(row, u) ((uint32_t)((row) * 64 + ((((u) ^ (((row) >> 1) & 3))) << 4)))

template<int BM>
__global__ void __launch_bounds__(256, 2) gemm_mma(
    const __nv_bfloat16* __restrict__ Ah, const __nv_bfloat16* __restrict__ Al,
    const __nv_bfloat16* __restrict__ Bh, const __nv_bfloat16* __restrict__ Bl,
    const float* __restrict__ res, float* __restrict__ C,
    __nv_bfloat16* __restrict__ oh, __nv_bfloat16* __restrict__ ol,
    int N, int K, int gated)
{
    constexpr int MI     = BM / 32;
    constexpr int STAGES = (BM == 128 ? 3 : 4);
    constexpr int ASZB   = BM  * 64;
    constexpr int BSZB   = 128 * 64;
    constexpr int STGB   = 2 * ASZB + 2 * BSZB;

    extern __shared__ __align__(16) __nv_bfloat16 sm[];
    const int tid = threadIdx.x, lane = tid & 31, w = tid >> 5;
    const int wr = w & 1, wc = w >> 1;
    const int bm = blockIdx.y * BM, bn = blockIdx.x * 128;
    const int NK = K >> 5;
    const uint32_t sbase = smem_to_u32(sm);

    const __nv_bfloat16* gAh = Ah + (size_t)bm * K;
    const __nv_bfloat16* gAl = Al + (size_t)bm * K;
    const __nv_bfloat16* gBh = Bh + (size_t)bn * K;
    const __nv_bfloat16* gBl = Bl + (size_t)bn * K;

    float acc[MI][4][4];
#pragma unroll
    for (int a = 0; a < MI; a++)
#pragma unroll
        for (int b = 0; b < 4; b++)
#pragma unroll
            for (int c = 0; c < 4; c++) acc[a][b][c] = 0.f;

    auto issue = [&](int st, int kc) {
        uint32_t sb = sbase + st * STGB;
        int ko = kc * 32;
#pragma unroll
        for (int c = tid; c < BM * 4; c += 256) {
            int r = c >> 2, u = c & 3;
            uint32_t d = SWZ(r, u);
            CPASYNC(sb + d,        gAh + (size_t)r * K + ko + u * 8);
            CPASYNC(sb + ASZB + d, gAl + (size_t)r * K + ko + u * 8);
        }
#pragma unroll
        for (int c = tid; c < 512; c += 256) {
            int r = c >> 2, u = c & 3;
            uint32_t d = SWZ(r, u);
            CPASYNC(sb + 2 * ASZB + d,        gBh + (size_t)r * K + ko + u * 8);
            CPASYNC(sb + 2 * ASZB + BSZB + d, gBl + (size_t)r * K + ko + u * 8);
        }
    };

#pragma unroll
    for (int s = 0; s < STAGES - 1; s++) { issue(s, s); CPCOMMIT(); }

    const int lj = lane >> 3, lr = lane & 7;

    for (int kc = 0; kc < NK; kc++) {
        int rem = NK - 1 - kc;
        if (rem >= STAGES - 2) {
            if (STAGES == 4) CPWAIT2(); else CPWAIT1();
        } else if (rem == 1) CPWAIT1();
        else CPWAIT0();
        __syncthreads();
        if (kc + STAGES - 1 < NK) { issue((kc + STAGES - 1) % STAGES, kc + STAGES - 1); CPCOMMIT(); }

        uint32_t sb = sbase + (kc % STAGES) * STGB;
        uint32_t aH = sb, aL = sb + ASZB;
        uint32_t bH = sb + 2 * ASZB, bL = sb + 2 * ASZB + BSZB;

#pragma unroll
        for (int ks = 0; ks < 2; ks++) {
            uint32_t ahf[MI][4], alf[MI][4], bhf[2][4], blf[2][4];
#pragma unroll
            for (int mi = 0; mi < MI; mi++) {
                int mrow = wr * (BM / 2) + mi * 16 + (lj & 1) * 8 + lr;
                int u = ks * 2 + (lj >> 1);
                uint32_t off = SWZ(mrow, u);
                LDSM4(ahf[mi], aH + off);
                LDSM4(alf[mi], aL + off);
            }
#pragma unroll
            for (int bt = 0; bt < 2; bt++) {
                int nrow = wc * 32 + bt * 16 + (lj >> 1) * 8 + lr;
                int u = ks * 2 + (lj & 1);
                uint32_t off = SWZ(nrow, u);
                LDSM4(bhf[bt], bH + off);
                LDSM4(blf[bt], bL + off);
            }
#pragma unroll
            for (int mi = 0; mi < MI; mi++)
#pragma unroll
                for (int bt = 0; bt < 2; bt++)
#pragma unroll
                    for (int hf = 0; hf < 2; hf++)
                        MMA_BF16(acc[mi][bt * 2 + hf], ahf[mi],
                                 bhf[bt][hf * 2], bhf[bt][hf * 2 + 1]);
#pragma unroll
            for (int mi = 0; mi < MI; mi++)
#pragma unroll
                for (int bt = 0; bt < 2; bt++)
#pragma unroll
                    for (int hf = 0; hf < 2; hf++)
                        MMA_BF16(acc[mi][bt * 2 + hf], ahf[mi],
                                 blf[bt][hf * 2], blf[bt][hf * 2 + 1]);
#pragma unroll
            for (int mi = 0; mi < MI; mi++)
#pragma unroll
                for (int bt = 0; bt < 2; bt++)
#pragma unroll
                    for (int hf = 0; hf < 2; hf++)
                        MMA_BF16(acc[mi][bt * 2 + hf], alf[mi],
                                 bhf[bt][hf * 2], bhf[bt][hf * 2 + 1]);
        }
    }

#pragma unroll
    for (int mi = 0; mi < MI; mi++) {
        int row0 = bm + wr * (BM / 2) + mi * 16 + (lane >> 2);
#pragma unroll
        for (int nt = 0; nt < 4; nt++) {
            int col = bn + wc * 32 + nt * 8 + (lane & 3) * 2;
            size_t i0 = (size_t)row0 * N + col;
            size_t i1 = (size_t)(row0 + 8) * N + col;
            float2 v0 = make_float2(acc[mi][nt][0], acc[mi][nt][1]);
            float2 v1 = make_float2(acc[mi][nt][2], acc[mi][nt][3]);
            if (res) {
                float2 a0 = *reinterpret_cast<const float2*>(res + i0);
                float2 a1 = *reinterpret_cast<const float2*>(res + i1);
                v0.x += a0.x; v0.y += a0.y; v1.x += a1.x; v1.y += a1.y;
            }
            if (C) {
                *reinterpret_cast<float2*>(C + i0) = v0;
                *reinterpret_cast<float2*>(C + i1) = v1;
            }
            if (gated) {
                int oc = col >> 1;
                int No = N >> 1;
                float g0 = 0.5f * v0.y * (1.0f + erff(v0.y * 0.7071067811865475f));
                float g1 = 0.5f * v1.y * (1.0f + erff(v1.y * 0.7071067811865475f));
                float r0v = v0.x * g0, r1v = v1.x * g1;
                __nv_bfloat16 h, l;
                bsplit(r0v, h, l);
                oh[(size_t)row0 * No + oc] = h; ol[(size_t)row0 * No + oc] = l;
                bsplit(r1v, h, l);
                oh[(size_t)(row0 + 8) * No + oc] = h; ol[(size_t)(row0 + 8) * No + oc] = l;
            } else if (oh) {
                __nv_bfloat16 h0, l0, h1, l1;
                bsplit(v0.x, h0, l0); bsplit(v0.y, h1, l1);
                *reinterpret_cast<uint32_t*>(oh + i0) = pack2(h0, h1);
                *reinterpret_cast<uint32_t*>(ol + i0) = pack2(l0, l1);
                bsplit(v1.x, h0, l0); bsplit(v1.y, h1, l1);
                *reinterpret_cast<uint32_t*>(oh + i1) = pack2(h0, h1);
                *reinterpret_cast<uint32_t*>(ol + i1) = pack2(l0, l1);
            }
        }
    }
}

#define GSMEM128 (3 * (2 * 128 * 64 + 2 * 128 * 64))
#define GSMEM64  (4 * (2 * 64 * 64 + 2 * 128 * 64))

// ------------------------------ launch ----------------------------------------
extern "C" void kernel_launch(void* const* d_in, const int* in_sizes, int n_in,
                              void* d_out, int out_size)
{
    (void)in_sizes; (void)n_in; (void)out_size;
    const float* x          = (const float*)d_in[0];
    const float* attn_gamma = (const float*)d_in[1];
    const float* wq         = (const float*)d_in[2];
    const float* wkv        = (const float*)d_in[3];
    const float* q_scale    = (const float*)d_in[4];
    const float* k_scale    = (const float*)d_in[5];
    const float* wo         = (const float*)d_in[6];
    const float* ff_gamma   = (const float*)d_in[7];
    const float* ff_beta    = (const float*)d_in[8];
    const float* wff1       = (const float*)d_in[9];
    const float* wff2       = (const float*)d_in[10];
    float* xo = (float*)d_out;

    float *q, *kv, *u;
    __nv_bfloat16 *ah, *al, *xh, *xl;
    __nv_bfloat16 *wth, *wtl, *wth2, *wtl2, *wtqh, *wtql, *wtoh, *wtol, *wtkh, *wtkl;
    __nv_bfloat16 *qh, *ql, *kh, *kl, *vh, *vl;
    cudaGetSymbolAddress((void**)&q,    g_q);
    cudaGetSymbolAddress((void**)&kv,   g_kv);
    cudaGetSymbolAddress((void**)&u,    g_u);
    cudaGetSymbolAddress((void**)&ah,   g_ah);
    cudaGetSymbolAddress((void**)&al,   g_al);
    cudaGetSymbolAddress((void**)&xh,   g_xh);
    cudaGetSymbolAddress((void**)&xl,   g_xl);
    cudaGetSymbolAddress((void**)&wth,  g_wth);
    cudaGetSymbolAddress((void**)&wtl,  g_wtl);
    cudaGetSymbolAddress((void**)&wth2, g_wth2);
    cudaGetSymbolAddress((void**)&wtl2, g_wtl2);
    cudaGetSymbolAddress((void**)&wtqh, g_wtqh);
    cudaGetSymbolAddress((void**)&wtql, g_wtql);
    cudaGetSymbolAddress((void**)&wtoh, g_wtoh);
    cudaGetSymbolAddress((void**)&wtol, g_wtol);
    cudaGetSymbolAddress((void**)&wtkh, g_wtkh);
    cudaGetSymbolAddress((void**)&wtkl, g_wtkl);
    cudaGetSymbolAddress((void**)&qh,   g_qh);
    cudaGetSymbolAddress((void**)&ql,   g_ql);
    cudaGetSymbolAddress((void**)&kh,   g_kh);
    cudaGetSymbolAddress((void**)&kl,   g_kl);
    cudaGetSymbolAddress((void**)&vh,   g_vh);
    cudaGetSymbolAddress((void**)&vl,   g_vl);
    __nv_bfloat16* gh = (__nv_bfloat16*)u;
    __nv_bfloat16* gl = gh + (size_t)MTOK * FFI;

    static cudaStream_t s2 = nullptr;
    static cudaEvent_t evs[16];
    if (!s2) {
        cudaStreamCreate(&s2);
        for (int i = 0; i < 16; i++)
            cudaEventCreateWithFlags(&evs[i], cudaEventDisableTiming);
        cudaFuncSetAttribute(gemm_mma<128>,
            cudaFuncAttributeMaxDynamicSharedMemorySize, GSMEM128);
        cudaFuncSetAttribute(gemm_mma<64>,
            cudaFuncAttributeMaxDynamicSharedMemorySize, GSMEM64);
    }

    cudaMemcpyAsync(xo, x, (size_t)MTOK * DIMM * sizeof(float),
                    cudaMemcpyDeviceToDevice);
    split_kernel<<<(MTOK * DIMM) / 256, 256>>>(xo, xh, xl);
    cudaEventRecord(evs[15], 0);   // eX for layer 0

    for (int i = 0; i < 4; i++) {
        cudaEvent_t eX   = (i == 0) ? evs[15] : evs[(i - 1) * 3 + 2];
        cudaEvent_t eWq  = evs[i * 3 + 0];
        cudaEvent_t eKV  = evs[i * 3 + 1];
        cudaEvent_t eXn  = evs[i * 3 + 2];

        // s2: q-weight transpose, then full kv chain (gated on prev layer end)
        cudaStreamWaitEvent(s2, eX, 0);
        wtrans_kernel<<<dim3(24, 24), 256, 0, s2>>>(
            wq + (size_t)i * 768 * 768, wtqh, wtql, 768, 768, 0);
        cudaEventRecord(eWq, s2);
        wtrans_kernel<<<dim3(48, 24), 256, 0, s2>>>(
            wkv + (size_t)i * 768 * 1536, wtkh, wtkl, 768, 1536, 0);
        gemm_mma<128><<<dim3(12, 32), 256, GSMEM128, s2>>>(
            xh, xl, wtkh, wtkl, nullptr, kv, nullptr, nullptr, 1536, 768, 0);
        rope_split_kernel<<<dim3(MTOK, 3), 256, 0, s2>>>(
            kv, 2 * DIMM, k_scale + (size_t)i * DHEAD, 1.0f, kh, kl);
        vtrans_split_kernel<<<dim3(NSEQ / 32, BHTOT), 256, 0, s2>>>(kv, vh, vl);
        cudaEventRecord(eKV, s2);

        // d: q chain + weight transposes fill the kv wait, then attn + FF
        ln_kernel<<<MTOK, 256>>>(xo, attn_gamma + (size_t)i * DIMM, nullptr, ah, al);
        cudaStreamWaitEvent(0, eWq, 0);
        gemm_mma<64><<<dim3(6, 64), 256, GSMEM64>>>(
            ah, al, wtqh, wtql, nullptr, q, nullptr, nullptr, 768, 768, 0);
        rope_split_kernel<<<dim3(MTOK, 3), 256>>>(
            q, DIMM, q_scale + (size_t)i * DHEAD, 8.0f, qh, ql);
        wtrans_kernel<<<dim3(24, 24), 256>>>(
            wo + (size_t)i * 768 * 768, wtoh, wtol, 768, 768, 0);
        wtrans_kernel<<<dim3(128, 24), 256>>>(
            wff1 + (size_t)i * 768 * 4096, wth, wtl, 768, 4096, 1);
        wtrans_kernel<<<dim3(24, 64), 256>>>(
            wff2 + (size_t)i * 2048 * 768, wth2, wtl2, 2048, 768, 0);
        cudaStreamWaitEvent(0, eKV, 0);
        attn_tc_kernel<<<dim3(NSEQ / 64, BHTOT), 128>>>(
            qh, ql, kh, kl, vh, vl, ah, al);
        gemm_mma<64><<<dim3(6, 64), 256, GSMEM64>>>(
            ah, al, wtoh, wtol, xo, xo, nullptr, nullptr, 768, 768, 0);
        ln_kernel<<<MTOK, 256>>>(xo, ff_gamma + (size_t)i * DIMM,
                                 ff_beta + (size_t)i * DIMM, ah, al);
        gemm_mma<128><<<dim3(32, 32), 256, GSMEM128>>>(
            ah, al, wth, wtl, nullptr, nullptr, gh, gl, 4096, 768, 1);
        gemm_mma<128><<<dim3(6, 32), 256, GSMEM128>>>(
            gh, gl, wth2, wtl2, xo, xo, xh, xl, 768, 2048, 0);
        cudaEventRecord(eXn, 0);
    }
}